// round 11
// baseline (speedup 1.0000x reference)
#include <cuda_runtime.h>
#include <cuda_fp16.h>
#include <cstdint>

#define N_NODES 100000
#define N_EDGES 3200000
#define DIM     256

// ---------------------------------------------------------------------------
// Static device scratch (no runtime allocation allowed)
// ---------------------------------------------------------------------------
__device__ __half2 g_Yh[(size_t)N_NODES * (DIM / 2)];  // X @ W^T fp16 (51.2 MB)
__device__ uint2 g_edgeS[N_EDGES];                     // sorted (col, val) 25.6 MB
__device__ int   g_cnt[N_NODES];                       // per-row degree
__device__ int   g_off[N_NODES];                       // exclusive prefix
__device__ int   g_cur[N_NODES];                       // scatter cursor

// ---------------------------------------------------------------------------
// Kernel A: zero counters + cursors
// ---------------------------------------------------------------------------
__global__ void __launch_bounds__(256) zero_kernel() {
    int i = blockIdx.x * blockDim.x + threadIdx.x;
    if (i < N_NODES) { g_cnt[i] = 0; g_cur[i] = 0; }
}

// ---------------------------------------------------------------------------
// Kernel B: histogram of edge destination rows
// ---------------------------------------------------------------------------
__global__ void __launch_bounds__(256) hist_kernel(const int* __restrict__ erow) {
    int i = blockIdx.x * blockDim.x + threadIdx.x;
    if (i < N_EDGES) atomicAdd(&g_cnt[erow[i]], 1);
}

// ---------------------------------------------------------------------------
// Kernel C: single-block chunked exclusive scan of g_cnt -> g_off
// ---------------------------------------------------------------------------
#define SCAN_THREADS 1024
#define SCAN_CHUNK   ((N_NODES + SCAN_THREADS - 1) / SCAN_THREADS)   // 98

__global__ void __launch_bounds__(SCAN_THREADS) scan_kernel() {
    __shared__ int sums[SCAN_THREADS];
    const int t     = threadIdx.x;
    const int start = t * SCAN_CHUNK;
    const int end   = min(start + SCAN_CHUNK, N_NODES);

    int s = 0;
    for (int i = start; i < end; i++) s += g_cnt[i];
    sums[t] = s;
    __syncthreads();

    for (int d = 1; d < SCAN_THREADS; d <<= 1) {
        int v = 0;
        if (t >= d) v = sums[t - d];
        __syncthreads();
        if (t >= d) sums[t] += v;
        __syncthreads();
    }

    int run = sums[t] - s;
    for (int i = start; i < end; i++) {
        g_off[i] = run;
        run += g_cnt[i];
    }
}

// ---------------------------------------------------------------------------
// Kernel D: scatter edges into row-sorted order (packed 8B records)
// ---------------------------------------------------------------------------
__global__ void __launch_bounds__(256) sort_scatter_kernel(const int* __restrict__ erow,
                                                           const int* __restrict__ ecol,
                                                           const float* __restrict__ eval) {
    int i = blockIdx.x * blockDim.x + threadIdx.x;
    if (i >= N_EDGES) return;
    int r   = erow[i];
    int idx = atomicAdd(&g_cur[r], 1);
    int p   = g_off[r] + idx;
    g_edgeS[p] = make_uint2((unsigned)ecol[i], __float_as_uint(eval[i]));
}

// ---------------------------------------------------------------------------
// Kernel E: Y = fp16(X @ W^T) via tensor cores (mma.m16n8k16, fp32 accum).
// Block tile 128x128, K-tile 32. 8 warps: 2 (M) x 4 (N); warp tile 64x32.
// ---------------------------------------------------------------------------
#define GBM 128
#define GBN 128
#define GBK 32
#define TSTR 40   // smem row stride in halves (80 B: conflict-free for ldmatrix)

__device__ __forceinline__ uint32_t smem_u32(const void* p) {
    return (uint32_t)__cvta_generic_to_shared(p);
}

__global__ void __launch_bounds__(256) gemm_tc_kernel(const float* __restrict__ X,
                                                      const float* __restrict__ W,
                                                      int M) {
    __shared__ __half As[GBM * TSTR];
    __shared__ __half Bs[GBN * TSTR];

    const int tid  = threadIdx.x;
    const int warp = tid >> 5;
    const int lane = tid & 31;
    const int wm   = warp >> 2;
    const int wn   = warp & 3;
    const int bm0  = blockIdx.y * GBM;
    const int bn0  = blockIdx.x * GBN;

    float acc[4][4][4];
#pragma unroll
    for (int mf = 0; mf < 4; mf++)
#pragma unroll
        for (int nf = 0; nf < 4; nf++)
#pragma unroll
            for (int q = 0; q < 4; q++) acc[mf][nf][q] = 0.0f;

    const int lrow = tid >> 3;
    const int lf4  = tid & 7;

    for (int kk = 0; kk < DIM; kk += GBK) {
#pragma unroll
        for (int p = 0; p < 4; p++) {
            int r  = lrow + p * 32;
            int gm = bm0 + r;
            float4 v = make_float4(0.f, 0.f, 0.f, 0.f);
            if (gm < M)
                v = *reinterpret_cast<const float4*>(X + (size_t)gm * DIM + kk + lf4 * 4);
            __half2 h0 = __floats2half2_rn(v.x, v.y);
            __half2 h1 = __floats2half2_rn(v.z, v.w);
            uint2 pk;
            pk.x = *reinterpret_cast<uint32_t*>(&h0);
            pk.y = *reinterpret_cast<uint32_t*>(&h1);
            *reinterpret_cast<uint2*>(&As[r * TSTR + lf4 * 4]) = pk;
        }
#pragma unroll
        for (int p = 0; p < 4; p++) {
            int r = lrow + p * 32;
            float4 v = *reinterpret_cast<const float4*>(W + (size_t)(bn0 + r) * DIM + kk + lf4 * 4);
            __half2 h0 = __floats2half2_rn(v.x, v.y);
            __half2 h1 = __floats2half2_rn(v.z, v.w);
            uint2 pk;
            pk.x = *reinterpret_cast<uint32_t*>(&h0);
            pk.y = *reinterpret_cast<uint32_t*>(&h1);
            *reinterpret_cast<uint2*>(&Bs[r * TSTR + lf4 * 4]) = pk;
        }
        __syncthreads();

#pragma unroll
        for (int ks = 0; ks < 2; ks++) {
            const int k0 = ks * 16;
            uint32_t a[4][4];
            uint32_t bfr[4][2];

#pragma unroll
            for (int mf = 0; mf < 4; mf++) {
                int row = wm * 64 + mf * 16 + (lane & 15);
                int col = k0 + (lane >> 4) * 8;
                uint32_t addr = smem_u32(&As[row * TSTR + col]);
                asm volatile("ldmatrix.sync.aligned.m8n8.x4.shared.b16 {%0,%1,%2,%3}, [%4];"
                             : "=r"(a[mf][0]), "=r"(a[mf][1]), "=r"(a[mf][2]), "=r"(a[mf][3])
                             : "r"(addr));
            }
#pragma unroll
            for (int nf = 0; nf < 4; nf++) {
                int row = wn * 32 + nf * 8 + (lane & 7);
                int col = k0 + ((lane >> 3) & 1) * 8;
                uint32_t addr = smem_u32(&Bs[row * TSTR + col]);
                asm volatile("ldmatrix.sync.aligned.m8n8.x2.shared.b16 {%0,%1}, [%2];"
                             : "=r"(bfr[nf][0]), "=r"(bfr[nf][1])
                             : "r"(addr));
            }
#pragma unroll
            for (int mf = 0; mf < 4; mf++)
#pragma unroll
                for (int nf = 0; nf < 4; nf++) {
                    asm volatile(
                        "mma.sync.aligned.m16n8k16.row.col.f32.f16.f16.f32 "
                        "{%0,%1,%2,%3}, {%4,%5,%6,%7}, {%8,%9}, {%0,%1,%2,%3};"
                        : "+f"(acc[mf][nf][0]), "+f"(acc[mf][nf][1]),
                          "+f"(acc[mf][nf][2]), "+f"(acc[mf][nf][3])
                        : "r"(a[mf][0]), "r"(a[mf][1]), "r"(a[mf][2]), "r"(a[mf][3]),
                          "r"(bfr[nf][0]), "r"(bfr[nf][1]));
                }
        }
        __syncthreads();
    }

    const int tr = lane >> 2;
    const int tc = lane & 3;
#pragma unroll
    for (int mf = 0; mf < 4; mf++)
#pragma unroll
        for (int nf = 0; nf < 4; nf++) {
            int col2 = (bn0 + wn * 32 + nf * 8) / 2 + tc;
            int r0 = bm0 + wm * 64 + mf * 16 + tr;
            if (r0 < M)
                g_Yh[(size_t)r0 * (DIM / 2) + col2] =
                    __floats2half2_rn(acc[mf][nf][0], acc[mf][nf][1]);
            int r1 = r0 + 8;
            if (r1 < M)
                g_Yh[(size_t)r1 * (DIM / 2) + col2] =
                    __floats2half2_rn(acc[mf][nf][2], acc[mf][nf][3]);
        }
}

// ---------------------------------------------------------------------------
// Kernel F: gather-reduce, 1 warp per node, 256-bit gathers, 2 edges/iter.
// Lanes 0-15 cover edge j's 512B row (32B each); lanes 16-31 cover edge j+1.
// Epilogue: shfl_xor(16) combines the two edge-parity partial sums.
// ---------------------------------------------------------------------------
__device__ __forceinline__ void ldg256_el(const void* p, uint32_t* r) {
    asm volatile("ld.global.nc.L2::evict_last.v8.b32 "
                 "{%0,%1,%2,%3,%4,%5,%6,%7}, [%8];"
                 : "=r"(r[0]), "=r"(r[1]), "=r"(r[2]), "=r"(r[3]),
                   "=r"(r[4]), "=r"(r[5]), "=r"(r[6]), "=r"(r[7])
                 : "l"(p));
}

__global__ void __launch_bounds__(256) gather_reduce_kernel(const float* __restrict__ b,
                                                            float* __restrict__ out) {
    const int warp   = (blockIdx.x * blockDim.x + threadIdx.x) >> 5;
    const int lane   = threadIdx.x & 31;
    const int par    = lane >> 4;      // which edge of the pair this lane serves
    const int lane16 = lane & 15;      // 32B chunk index within the 512B row
    if (warp >= N_NODES) return;

    const int start = g_off[warp];
    const int deg   = g_cnt[warp];

    // 16 features per lane: f = lane16*16 + q
    float acc[16];
#pragma unroll
    for (int q = 0; q < 16; q++) acc[q] = 0.0f;

    for (int base = 0; base < deg; base += 32) {
        const int rem = deg - base;
        const int lim = rem < 32 ? rem : 32;
        uint2 e = make_uint2(0u, 0u);   // zero val => lanes past lim contribute 0
        if (lane < lim) e = g_edgeS[start + base + lane];
#pragma unroll 2
        for (int j = 0; j < lim; j += 2) {
            // broadcast the pair of edges (j, j+1); j+1 may be zero-record
            const int   cc0 = (int)__shfl_sync(0xffffffffu, e.x, j);
            const float vv0 = __uint_as_float(__shfl_sync(0xffffffffu, e.y, j));
            const int   cc1 = (int)__shfl_sync(0xffffffffu, e.x, j + 1);
            const float vv1 = __uint_as_float(__shfl_sync(0xffffffffu, e.y, j + 1));
            const int   cc  = par ? cc1 : cc0;
            const float vv  = par ? vv1 : vv0;

            const __half2* src = g_Yh + (size_t)cc * (DIM / 2) + lane16 * 8;
            uint32_t p[8];
            ldg256_el(src, p);
            const __half2* h = reinterpret_cast<const __half2*>(p);
#pragma unroll
            for (int q = 0; q < 8; q++) {
                float2 f = __half22float2(h[q]);
                acc[q * 2 + 0] = fmaf(vv, f.x, acc[q * 2 + 0]);
                acc[q * 2 + 1] = fmaf(vv, f.y, acc[q * 2 + 1]);
            }
        }
    }

    // combine the two edge-parity partials: lanes l and l^16 own same features
#pragma unroll
    for (int q = 0; q < 16; q++)
        acc[q] += __shfl_xor_sync(0xffffffffu, acc[q], 16);

    // write: lane handles features [lane16*16 + par*8, +8) = 2 float4
    const int f0 = lane16 * 16 + par * 8;
    const float4* bv = reinterpret_cast<const float4*>(b + f0);
    float4 b0 = bv[0];
    float4 b1 = bv[1];
    const int a0 = par * 8;
    float4 o0 = make_float4(acc[a0 + 0] + b0.x, acc[a0 + 1] + b0.y,
                            acc[a0 + 2] + b0.z, acc[a0 + 3] + b0.w);
    float4 o1 = make_float4(acc[a0 + 4] + b1.x, acc[a0 + 5] + b1.y,
                            acc[a0 + 6] + b1.z, acc[a0 + 7] + b1.w);

    float4* dst = reinterpret_cast<float4*>(out + (size_t)warp * DIM + f0);
    dst[0] = o0;
    dst[1] = o1;
}

// ---------------------------------------------------------------------------
// Launch (single stream). Inputs: X, edge_row, edge_col, edge_val, W, b
// ---------------------------------------------------------------------------
extern "C" void kernel_launch(void* const* d_in, const int* in_sizes, int n_in,
                              void* d_out, int out_size) {
    const float* X    = (const float*)d_in[0];
    const int*   erow = (const int*)  d_in[1];
    const int*   ecol = (const int*)  d_in[2];
    const float* eval = (const float*)d_in[3];
    const float* W    = (const float*)d_in[4];
    const float* b    = (const float*)d_in[5];
    float*       out  = (float*)d_out;

    // 1) counting sort of edges by destination row
    zero_kernel<<<(N_NODES + 255) / 256, 256>>>();
    hist_kernel<<<(N_EDGES + 255) / 256, 256>>>(erow);
    scan_kernel<<<1, SCAN_THREADS>>>();
    sort_scatter_kernel<<<(N_EDGES + 255) / 256, 256>>>(erow, ecol, eval);

    // 2) Y = fp16(X @ W^T) on tensor cores
    {
        dim3 grid(DIM / GBN, (N_NODES + GBM - 1) / GBM);
        gemm_tc_kernel<<<grid, 256>>>(X, W, N_NODES);
    }

    // 3) out[n] = b + sum val * Y[col]   (1 warp/node, 256-bit gathers)
    {
        int warps_per_block = 256 / 32;
        int blocks = (N_NODES + warps_per_block - 1) / warps_per_block;
        gather_reduce_kernel<<<blocks, 256>>>(b, out);
    }
}

// round 12
// speedup vs baseline: 1.1032x; 1.1032x over previous
#include <cuda_runtime.h>
#include <cuda_fp16.h>
#include <cstdint>

#define N_NODES 100000
#define N_EDGES 3200000
#define DIM     256

// ---------------------------------------------------------------------------
// Static device scratch (no runtime allocation allowed)
// ---------------------------------------------------------------------------
__device__ __half2 g_Yh[(size_t)N_NODES * (DIM / 2)];  // X @ W^T fp16 (51.2 MB)
__device__ uint2 g_edgeS[N_EDGES];                     // sorted (col, val) 25.6 MB
__device__ int   g_cnt[N_NODES];                       // per-row degree
__device__ int   g_off[N_NODES];                       // exclusive prefix
__device__ int   g_cur[N_NODES];                       // scatter cursor

// ---------------------------------------------------------------------------
// Kernel A: zero counters + cursors
// ---------------------------------------------------------------------------
__global__ void __launch_bounds__(256) zero_kernel() {
    int i = blockIdx.x * blockDim.x + threadIdx.x;
    if (i < N_NODES) { g_cnt[i] = 0; g_cur[i] = 0; }
}

// ---------------------------------------------------------------------------
// Kernel B: histogram of edge destination rows
// ---------------------------------------------------------------------------
__global__ void __launch_bounds__(256) hist_kernel(const int* __restrict__ erow) {
    int i = blockIdx.x * blockDim.x + threadIdx.x;
    if (i < N_EDGES) atomicAdd(&g_cnt[erow[i]], 1);
}

// ---------------------------------------------------------------------------
// Kernel C: single-block chunked exclusive scan of g_cnt -> g_off
// ---------------------------------------------------------------------------
#define SCAN_THREADS 1024
#define SCAN_CHUNK   ((N_NODES + SCAN_THREADS - 1) / SCAN_THREADS)   // 98

__global__ void __launch_bounds__(SCAN_THREADS) scan_kernel() {
    __shared__ int sums[SCAN_THREADS];
    const int t     = threadIdx.x;
    const int start = t * SCAN_CHUNK;
    const int end   = min(start + SCAN_CHUNK, N_NODES);

    int s = 0;
    for (int i = start; i < end; i++) s += g_cnt[i];
    sums[t] = s;
    __syncthreads();

    for (int d = 1; d < SCAN_THREADS; d <<= 1) {
        int v = 0;
        if (t >= d) v = sums[t - d];
        __syncthreads();
        if (t >= d) sums[t] += v;
        __syncthreads();
    }

    int run = sums[t] - s;
    for (int i = start; i < end; i++) {
        g_off[i] = run;
        run += g_cnt[i];
    }
}

// ---------------------------------------------------------------------------
// Kernel D: scatter edges into row-sorted order (packed 8B records)
// ---------------------------------------------------------------------------
__global__ void __launch_bounds__(256) sort_scatter_kernel(const int* __restrict__ erow,
                                                           const int* __restrict__ ecol,
                                                           const float* __restrict__ eval) {
    int i = blockIdx.x * blockDim.x + threadIdx.x;
    if (i >= N_EDGES) return;
    int r   = erow[i];
    int idx = atomicAdd(&g_cur[r], 1);
    int p   = g_off[r] + idx;
    g_edgeS[p] = make_uint2((unsigned)ecol[i], __float_as_uint(eval[i]));
}

// ---------------------------------------------------------------------------
// Kernel E: Y = fp16(X @ W^T) via tensor cores (mma.m16n8k16, fp32 accum).
// Block tile 128x128, K-tile 32. 8 warps: 2 (M) x 4 (N); warp tile 64x32.
// ---------------------------------------------------------------------------
#define GBM 128
#define GBN 128
#define GBK 32
#define TSTR 40   // smem row stride in halves (80 B: conflict-free for ldmatrix)

__device__ __forceinline__ uint32_t smem_u32(const void* p) {
    return (uint32_t)__cvta_generic_to_shared(p);
}

__global__ void __launch_bounds__(256) gemm_tc_kernel(const float* __restrict__ X,
                                                      const float* __restrict__ W,
                                                      int M) {
    __shared__ __half As[GBM * TSTR];
    __shared__ __half Bs[GBN * TSTR];

    const int tid  = threadIdx.x;
    const int warp = tid >> 5;
    const int lane = tid & 31;
    const int wm   = warp >> 2;
    const int wn   = warp & 3;
    const int bm0  = blockIdx.y * GBM;
    const int bn0  = blockIdx.x * GBN;

    float acc[4][4][4];
#pragma unroll
    for (int mf = 0; mf < 4; mf++)
#pragma unroll
        for (int nf = 0; nf < 4; nf++)
#pragma unroll
            for (int q = 0; q < 4; q++) acc[mf][nf][q] = 0.0f;

    const int lrow = tid >> 3;
    const int lf4  = tid & 7;

    for (int kk = 0; kk < DIM; kk += GBK) {
#pragma unroll
        for (int p = 0; p < 4; p++) {
            int r  = lrow + p * 32;
            int gm = bm0 + r;
            float4 v = make_float4(0.f, 0.f, 0.f, 0.f);
            if (gm < M)
                v = *reinterpret_cast<const float4*>(X + (size_t)gm * DIM + kk + lf4 * 4);
            __half2 h0 = __floats2half2_rn(v.x, v.y);
            __half2 h1 = __floats2half2_rn(v.z, v.w);
            uint2 pk;
            pk.x = *reinterpret_cast<uint32_t*>(&h0);
            pk.y = *reinterpret_cast<uint32_t*>(&h1);
            *reinterpret_cast<uint2*>(&As[r * TSTR + lf4 * 4]) = pk;
        }
#pragma unroll
        for (int p = 0; p < 4; p++) {
            int r = lrow + p * 32;
            float4 v = *reinterpret_cast<const float4*>(W + (size_t)(bn0 + r) * DIM + kk + lf4 * 4);
            __half2 h0 = __floats2half2_rn(v.x, v.y);
            __half2 h1 = __floats2half2_rn(v.z, v.w);
            uint2 pk;
            pk.x = *reinterpret_cast<uint32_t*>(&h0);
            pk.y = *reinterpret_cast<uint32_t*>(&h1);
            *reinterpret_cast<uint2*>(&Bs[r * TSTR + lf4 * 4]) = pk;
        }
        __syncthreads();

#pragma unroll
        for (int ks = 0; ks < 2; ks++) {
            const int k0 = ks * 16;
            uint32_t a[4][4];
            uint32_t bfr[4][2];

#pragma unroll
            for (int mf = 0; mf < 4; mf++) {
                int row = wm * 64 + mf * 16 + (lane & 15);
                int col = k0 + (lane >> 4) * 8;
                uint32_t addr = smem_u32(&As[row * TSTR + col]);
                asm volatile("ldmatrix.sync.aligned.m8n8.x4.shared.b16 {%0,%1,%2,%3}, [%4];"
                             : "=r"(a[mf][0]), "=r"(a[mf][1]), "=r"(a[mf][2]), "=r"(a[mf][3])
                             : "r"(addr));
            }
#pragma unroll
            for (int nf = 0; nf < 4; nf++) {
                int row = wn * 32 + nf * 8 + (lane & 7);
                int col = k0 + ((lane >> 3) & 1) * 8;
                uint32_t addr = smem_u32(&Bs[row * TSTR + col]);
                asm volatile("ldmatrix.sync.aligned.m8n8.x2.shared.b16 {%0,%1}, [%2];"
                             : "=r"(bfr[nf][0]), "=r"(bfr[nf][1])
                             : "r"(addr));
            }
#pragma unroll
            for (int mf = 0; mf < 4; mf++)
#pragma unroll
                for (int nf = 0; nf < 4; nf++) {
                    asm volatile(
                        "mma.sync.aligned.m16n8k16.row.col.f32.f16.f16.f32 "
                        "{%0,%1,%2,%3}, {%4,%5,%6,%7}, {%8,%9}, {%0,%1,%2,%3};"
                        : "+f"(acc[mf][nf][0]), "+f"(acc[mf][nf][1]),
                          "+f"(acc[mf][nf][2]), "+f"(acc[mf][nf][3])
                        : "r"(a[mf][0]), "r"(a[mf][1]), "r"(a[mf][2]), "r"(a[mf][3]),
                          "r"(bfr[nf][0]), "r"(bfr[nf][1]));
                }
        }
        __syncthreads();
    }

    const int tr = lane >> 2;
    const int tc = lane & 3;
#pragma unroll
    for (int mf = 0; mf < 4; mf++)
#pragma unroll
        for (int nf = 0; nf < 4; nf++) {
            int col2 = (bn0 + wn * 32 + nf * 8) / 2 + tc;
            int r0 = bm0 + wm * 64 + mf * 16 + tr;
            if (r0 < M)
                g_Yh[(size_t)r0 * (DIM / 2) + col2] =
                    __floats2half2_rn(acc[mf][nf][0], acc[mf][nf][1]);
            int r1 = r0 + 8;
            if (r1 < M)
                g_Yh[(size_t)r1 * (DIM / 2) + col2] =
                    __floats2half2_rn(acc[mf][nf][2], acc[mf][nf][3]);
        }
}

// ---------------------------------------------------------------------------
// Kernel F: per-node gather-reduce (R6 form — the proven local optimum).
// One warp per node; each lane owns 8 floats (= one uint4 of 8 halves).
// ---------------------------------------------------------------------------
__global__ void __launch_bounds__(256) gather_reduce_kernel(const float* __restrict__ b,
                                                            float* __restrict__ out) {
    const int warp = (blockIdx.x * blockDim.x + threadIdx.x) >> 5;
    const int lane = threadIdx.x & 31;
    if (warp >= N_NODES) return;

    const int start = g_off[warp];
    const int deg   = g_cnt[warp];

    float acc[8] = {0.f, 0.f, 0.f, 0.f, 0.f, 0.f, 0.f, 0.f};

    for (int base = 0; base < deg; base += 32) {
        const int rem = deg - base;
        const int lim = rem < 32 ? rem : 32;
        uint2 e = make_uint2(0u, 0u);
        if (lane < lim) e = g_edgeS[start + base + lane];
#pragma unroll 4
        for (int j = 0; j < lim; j++) {
            const int   cc = (int)__shfl_sync(0xffffffffu, e.x, j);
            const float vv = __uint_as_float(__shfl_sync(0xffffffffu, e.y, j));
            const uint4* src = reinterpret_cast<const uint4*>(g_Yh + (size_t)cc * (DIM / 2));
            uint4 p = src[lane];
            const __half2* h = reinterpret_cast<const __half2*>(&p);
#pragma unroll
            for (int q = 0; q < 4; q++) {
                float2 f = __half22float2(h[q]);
                acc[q * 2 + 0] = fmaf(vv, f.x, acc[q * 2 + 0]);
                acc[q * 2 + 1] = fmaf(vv, f.y, acc[q * 2 + 1]);
            }
        }
    }

    const float4* bv = reinterpret_cast<const float4*>(b);
    float4 b0 = bv[lane * 2];
    float4 b1 = bv[lane * 2 + 1];
    float4 o0 = make_float4(acc[0] + b0.x, acc[1] + b0.y, acc[2] + b0.z, acc[3] + b0.w);
    float4 o1 = make_float4(acc[4] + b1.x, acc[5] + b1.y, acc[6] + b1.z, acc[7] + b1.w);

    float4* dst = reinterpret_cast<float4*>(out + (size_t)warp * DIM);
    dst[lane * 2]     = o0;
    dst[lane * 2 + 1] = o1;
}

// ---------------------------------------------------------------------------
// Launch. Fork/join: sort chain on side stream overlaps the GEMM.
// Inputs: X, edge_row, edge_col, edge_val, W, b
// ---------------------------------------------------------------------------
extern "C" void kernel_launch(void* const* d_in, const int* in_sizes, int n_in,
                              void* d_out, int out_size) {
    const float* X    = (const float*)d_in[0];
    const int*   erow = (const int*)  d_in[1];
    const int*   ecol = (const int*)  d_in[2];
    const float* eval = (const float*)d_in[3];
    const float* W    = (const float*)d_in[4];
    const float* b    = (const float*)d_in[5];
    float*       out  = (float*)d_out;

    static cudaStream_t s_side = nullptr;
    static cudaEvent_t  ev_fork = nullptr, ev_join = nullptr;
    if (!s_side) {
        cudaStreamCreateWithFlags(&s_side, cudaStreamNonBlocking);
        cudaEventCreateWithFlags(&ev_fork, cudaEventDisableTiming);
        cudaEventCreateWithFlags(&ev_join, cudaEventDisableTiming);
    }

    // Fork side stream from the main stream
    cudaEventRecord(ev_fork, 0);
    cudaStreamWaitEvent(s_side, ev_fork, 0);

    // --- side stream: counting sort of edges by destination row ---
    zero_kernel<<<(N_NODES + 255) / 256, 256, 0, s_side>>>();
    hist_kernel<<<(N_EDGES + 255) / 256, 256, 0, s_side>>>(erow);
    scan_kernel<<<1, SCAN_THREADS, 0, s_side>>>();
    sort_scatter_kernel<<<(N_EDGES + 255) / 256, 256, 0, s_side>>>(erow, ecol, eval);

    // --- main stream: Y = fp16(X @ W^T) on tensor cores ---
    {
        dim3 grid(DIM / GBN, (N_NODES + GBM - 1) / GBM);
        gemm_tc_kernel<<<grid, 256>>>(X, W, N_NODES);
    }

    // Join: reduce needs both sorted edges and Y
    cudaEventRecord(ev_join, s_side);
    cudaStreamWaitEvent(0, ev_join, 0);

    // --- main stream: out[n] = b + sum val * Y[col] ---
    {
        int warps_per_block = 256 / 32;
        int blocks = (N_NODES + warps_per_block - 1) / warps_per_block;
        gather_reduce_kernel<<<blocks, 256>>>(b, out);
    }
}

// round 13
// speedup vs baseline: 1.1156x; 1.0113x over previous
#include <cuda_runtime.h>
#include <cuda_fp16.h>
#include <cstdint>

#define N_NODES 100000
#define N_EDGES 3200000
#define DIM     256

// ---------------------------------------------------------------------------
// Static device scratch (no runtime allocation allowed)
// ---------------------------------------------------------------------------
__device__ __half2 g_Yh[(size_t)N_NODES * (DIM / 2)];  // X @ W^T fp16 (51.2 MB)
__device__ uint2 g_edgeS[N_EDGES];                     // sorted (col, val) 25.6 MB
__device__ int   g_idx[N_EDGES];                       // per-edge slot within row
__device__ int   g_cnt[N_NODES];                       // per-row degree
__device__ int   g_off[N_NODES];                       // exclusive prefix

// ---------------------------------------------------------------------------
// Kernel A: zero counters
// ---------------------------------------------------------------------------
__global__ void __launch_bounds__(256) zero_kernel() {
    int i = blockIdx.x * blockDim.x + threadIdx.x;
    if (i < N_NODES) g_cnt[i] = 0;
}

// ---------------------------------------------------------------------------
// Kernel B: histogram of edge destination rows + record each edge's slot.
// The atomic here replaces the one previously paid in the scatter.
// ---------------------------------------------------------------------------
__global__ void __launch_bounds__(256) hist_kernel(const int* __restrict__ erow) {
    int i = blockIdx.x * blockDim.x + threadIdx.x;
    if (i < N_EDGES) g_idx[i] = atomicAdd(&g_cnt[erow[i]], 1);
}

// ---------------------------------------------------------------------------
// Kernel C: single-block chunked exclusive scan of g_cnt -> g_off
// ---------------------------------------------------------------------------
#define SCAN_THREADS 1024
#define SCAN_CHUNK   ((N_NODES + SCAN_THREADS - 1) / SCAN_THREADS)   // 98

__global__ void __launch_bounds__(SCAN_THREADS) scan_kernel() {
    __shared__ int sums[SCAN_THREADS];
    const int t     = threadIdx.x;
    const int start = t * SCAN_CHUNK;
    const int end   = min(start + SCAN_CHUNK, N_NODES);

    int s = 0;
    for (int i = start; i < end; i++) s += g_cnt[i];
    sums[t] = s;
    __syncthreads();

    for (int d = 1; d < SCAN_THREADS; d <<= 1) {
        int v = 0;
        if (t >= d) v = sums[t - d];
        __syncthreads();
        if (t >= d) sums[t] += v;
        __syncthreads();
    }

    int run = sums[t] - s;
    for (int i = start; i < end; i++) {
        g_off[i] = run;
        run += g_cnt[i];
    }
}

// ---------------------------------------------------------------------------
// Kernel D: scatter edges into row-sorted order — ATOMIC-FREE (slot
// precomputed in hist). Pure streaming loads + scattered 8B stores.
// ---------------------------------------------------------------------------
__global__ void __launch_bounds__(256) sort_scatter_kernel(const int* __restrict__ erow,
                                                           const int* __restrict__ ecol,
                                                           const float* __restrict__ eval) {
    int i = blockIdx.x * blockDim.x + threadIdx.x;
    if (i >= N_EDGES) return;
    int p = g_off[erow[i]] + g_idx[i];
    g_edgeS[p] = make_uint2((unsigned)ecol[i], __float_as_uint(eval[i]));
}

// ---------------------------------------------------------------------------
// Kernel E: Y = fp16(X @ W^T), tensor cores, SINGLE PASS over X.
// Block tile 64x256 (full N), K-tile 32. 8 warps: 2 (M) x 4 (N);
// warp tile 32x64. X read once from DRAM; W tiles re-read from L2.
// ---------------------------------------------------------------------------
#define GBM 64
#define GBN 256
#define GBK 32
#define TSTR 40   // smem row stride in halves (80 B: conflict-free for ldmatrix)

__device__ __forceinline__ uint32_t smem_u32(const void* p) {
    return (uint32_t)__cvta_generic_to_shared(p);
}

__global__ void __launch_bounds__(256) gemm_tc_kernel(const float* __restrict__ X,
                                                      const float* __restrict__ W,
                                                      int M) {
    __shared__ __half As[GBM * TSTR];   //  5.1 KB
    __shared__ __half Bs[GBN * TSTR];   // 20.5 KB

    const int tid  = threadIdx.x;
    const int warp = tid >> 5;
    const int lane = tid & 31;
    const int wm   = warp >> 2;       // 0..1 : M position (32 rows each)
    const int wn   = warp & 3;        // 0..3 : N position (64 cols each)
    const int bm0  = blockIdx.x * GBM;

    float acc[2][8][4];
#pragma unroll
    for (int mf = 0; mf < 2; mf++)
#pragma unroll
        for (int nf = 0; nf < 8; nf++)
#pragma unroll
            for (int q = 0; q < 4; q++) acc[mf][nf][q] = 0.0f;

    for (int kk = 0; kk < DIM; kk += GBK) {
        // --- A tile: 64 rows x 32 cols = 512 float4, 2 per thread ---
#pragma unroll
        for (int it = 0; it < 2; it++) {
            int idx = tid + 256 * it;
            int r   = idx >> 3;       // 0..63
            int f4  = idx & 7;
            int gm  = bm0 + r;
            float4 v = make_float4(0.f, 0.f, 0.f, 0.f);
            if (gm < M)
                v = *reinterpret_cast<const float4*>(X + (size_t)gm * DIM + kk + f4 * 4);
            __half2 h0 = __floats2half2_rn(v.x, v.y);
            __half2 h1 = __floats2half2_rn(v.z, v.w);
            uint2 pk;
            pk.x = *reinterpret_cast<uint32_t*>(&h0);
            pk.y = *reinterpret_cast<uint32_t*>(&h1);
            *reinterpret_cast<uint2*>(&As[r * TSTR + f4 * 4]) = pk;
        }
        // --- B tile: 256 rows x 32 cols = 2048 float4, 8 per thread ---
#pragma unroll
        for (int it = 0; it < 8; it++) {
            int idx = tid + 256 * it;
            int r   = idx >> 3;       // 0..255
            int f4  = idx & 7;
            float4 v = *reinterpret_cast<const float4*>(W + (size_t)r * DIM + kk + f4 * 4);
            __half2 h0 = __floats2half2_rn(v.x, v.y);
            __half2 h1 = __floats2half2_rn(v.z, v.w);
            uint2 pk;
            pk.x = *reinterpret_cast<uint32_t*>(&h0);
            pk.y = *reinterpret_cast<uint32_t*>(&h1);
            *reinterpret_cast<uint2*>(&Bs[r * TSTR + f4 * 4]) = pk;
        }
        __syncthreads();

#pragma unroll
        for (int ks = 0; ks < 2; ks++) {
            const int k0 = ks * 16;
            uint32_t a[2][4];
            uint32_t bfr[8][2];

#pragma unroll
            for (int mf = 0; mf < 2; mf++) {
                int row = wm * 32 + mf * 16 + (lane & 15);
                int col = k0 + (lane >> 4) * 8;
                uint32_t addr = smem_u32(&As[row * TSTR + col]);
                asm volatile("ldmatrix.sync.aligned.m8n8.x4.shared.b16 {%0,%1,%2,%3}, [%4];"
                             : "=r"(a[mf][0]), "=r"(a[mf][1]), "=r"(a[mf][2]), "=r"(a[mf][3])
                             : "r"(addr));
            }
#pragma unroll
            for (int nf = 0; nf < 8; nf++) {
                int row = wn * 64 + nf * 8 + (lane & 7);
                int col = k0 + ((lane >> 3) & 1) * 8;
                uint32_t addr = smem_u32(&Bs[row * TSTR + col]);
                asm volatile("ldmatrix.sync.aligned.m8n8.x2.shared.b16 {%0,%1}, [%2];"
                             : "=r"(bfr[nf][0]), "=r"(bfr[nf][1])
                             : "r"(addr));
            }
#pragma unroll
            for (int mf = 0; mf < 2; mf++)
#pragma unroll
                for (int nf = 0; nf < 8; nf++) {
                    asm volatile(
                        "mma.sync.aligned.m16n8k16.row.col.f32.f16.f16.f32 "
                        "{%0,%1,%2,%3}, {%4,%5,%6,%7}, {%8,%9}, {%0,%1,%2,%3};"
                        : "+f"(acc[mf][nf][0]), "+f"(acc[mf][nf][1]),
                          "+f"(acc[mf][nf][2]), "+f"(acc[mf][nf][3])
                        : "r"(a[mf][0]), "r"(a[mf][1]), "r"(a[mf][2]), "r"(a[mf][3]),
                          "r"(bfr[nf][0]), "r"(bfr[nf][1]));
                }
        }
        __syncthreads();
    }

    const int tr = lane >> 2;
    const int tc = lane & 3;
#pragma unroll
    for (int mf = 0; mf < 2; mf++)
#pragma unroll
        for (int nf = 0; nf < 8; nf++) {
            int col2 = (wn * 64 + nf * 8) / 2 + tc;
            int r0 = bm0 + wm * 32 + mf * 16 + tr;
            if (r0 < M)
                g_Yh[(size_t)r0 * (DIM / 2) + col2] =
                    __floats2half2_rn(acc[mf][nf][0], acc[mf][nf][1]);
            int r1 = r0 + 8;
            if (r1 < M)
                g_Yh[(size_t)r1 * (DIM / 2) + col2] =
                    __floats2half2_rn(acc[mf][nf][2], acc[mf][nf][3]);
        }
}

// ---------------------------------------------------------------------------
// Kernel F: per-node gather-reduce (R6 form — proven local optimum).
// One warp per node; each lane owns 8 floats (= one uint4 of 8 halves).
// ---------------------------------------------------------------------------
__global__ void __launch_bounds__(256) gather_reduce_kernel(const float* __restrict__ b,
                                                            float* __restrict__ out) {
    const int warp = (blockIdx.x * blockDim.x + threadIdx.x) >> 5;
    const int lane = threadIdx.x & 31;
    if (warp >= N_NODES) return;

    const int start = g_off[warp];
    const int deg   = g_cnt[warp];

    float acc[8] = {0.f, 0.f, 0.f, 0.f, 0.f, 0.f, 0.f, 0.f};

    for (int base = 0; base < deg; base += 32) {
        const int rem = deg - base;
        const int lim = rem < 32 ? rem : 32;
        uint2 e = make_uint2(0u, 0u);
        if (lane < lim) e = g_edgeS[start + base + lane];
#pragma unroll 4
        for (int j = 0; j < lim; j++) {
            const int   cc = (int)__shfl_sync(0xffffffffu, e.x, j);
            const float vv = __uint_as_float(__shfl_sync(0xffffffffu, e.y, j));
            const uint4* src = reinterpret_cast<const uint4*>(g_Yh + (size_t)cc * (DIM / 2));
            uint4 p = src[lane];
            const __half2* h = reinterpret_cast<const __half2*>(&p);
#pragma unroll
            for (int q = 0; q < 4; q++) {
                float2 f = __half22float2(h[q]);
                acc[q * 2 + 0] = fmaf(vv, f.x, acc[q * 2 + 0]);
                acc[q * 2 + 1] = fmaf(vv, f.y, acc[q * 2 + 1]);
            }
        }
    }

    const float4* bv = reinterpret_cast<const float4*>(b);
    float4 b0 = bv[lane * 2];
    float4 b1 = bv[lane * 2 + 1];
    float4 o0 = make_float4(acc[0] + b0.x, acc[1] + b0.y, acc[2] + b0.z, acc[3] + b0.w);
    float4 o1 = make_float4(acc[4] + b1.x, acc[5] + b1.y, acc[6] + b1.z, acc[7] + b1.w);

    float4* dst = reinterpret_cast<float4*>(out + (size_t)warp * DIM);
    dst[lane * 2]     = o0;
    dst[lane * 2 + 1] = o1;
}

// ---------------------------------------------------------------------------
// Launch (single stream — proven best). Inputs: X, edge_row, edge_col,
// edge_val, W, b
// ---------------------------------------------------------------------------
extern "C" void kernel_launch(void* const* d_in, const int* in_sizes, int n_in,
                              void* d_out, int out_size) {
    const float* X    = (const float*)d_in[0];
    const int*   erow = (const int*)  d_in[1];
    const int*   ecol = (const int*)  d_in[2];
    const float* eval = (const float*)d_in[3];
    const float* W    = (const float*)d_in[4];
    const float* b    = (const float*)d_in[5];
    float*       out  = (float*)d_out;

    // 1) counting sort of edges by destination row (scatter is atomic-free)
    zero_kernel<<<(N_NODES + 255) / 256, 256>>>();
    hist_kernel<<<(N_EDGES + 255) / 256, 256>>>(erow);
    scan_kernel<<<1, SCAN_THREADS>>>();
    sort_scatter_kernel<<<(N_EDGES + 255) / 256, 256>>>(erow, ecol, eval);

    // 2) Y = fp16(X @ W^T), single pass over X
    {
        int blocks = (N_NODES + GBM - 1) / GBM;
        gemm_tc_kernel<<<blocks, 256>>>(X, W, N_NODES);
    }

    // 3) out[n] = b + sum val * Y[col]   (atomic-free)
    {
        int warps_per_block = 256 / 32;
        int blocks = (N_NODES + warps_per_block - 1) / warps_per_block;
        gather_reduce_kernel<<<blocks, 256>>>(b, out);
    }
}

// round 14
// speedup vs baseline: 1.1740x; 1.0524x over previous
#include <cuda_runtime.h>
#include <cuda_fp16.h>
#include <cstdint>

#define N_NODES 100000
#define N_EDGES 3200000
#define DIM     256

// ---------------------------------------------------------------------------
// Static device scratch (no runtime allocation allowed)
// ---------------------------------------------------------------------------
__device__ __half2 g_Yh[(size_t)N_NODES * (DIM / 2)];  // X @ W^T fp16 (51.2 MB)
__device__ uint2 g_edgeS[N_EDGES];                     // sorted (col, val) 25.6 MB
__device__ int   g_idx[N_EDGES];                       // per-edge slot within row
__device__ int   g_cnt[N_NODES];                       // per-row degree
__device__ int   g_off[N_NODES];                       // exclusive prefix

// ---------------------------------------------------------------------------
// Kernel A: zero counters
// ---------------------------------------------------------------------------
__global__ void __launch_bounds__(256) zero_kernel() {
    int i = blockIdx.x * blockDim.x + threadIdx.x;
    if (i < N_NODES) g_cnt[i] = 0;
}

// ---------------------------------------------------------------------------
// Kernel B: histogram of edge destination rows + record each edge's slot.
// ---------------------------------------------------------------------------
__global__ void __launch_bounds__(256) hist_kernel(const int* __restrict__ erow) {
    int i = blockIdx.x * blockDim.x + threadIdx.x;
    if (i < N_EDGES) g_idx[i] = atomicAdd(&g_cnt[erow[i]], 1);
}

// ---------------------------------------------------------------------------
// Kernel C: single-block chunked exclusive scan of g_cnt -> g_off
// ---------------------------------------------------------------------------
#define SCAN_THREADS 1024
#define SCAN_CHUNK   ((N_NODES + SCAN_THREADS - 1) / SCAN_THREADS)   // 98

__global__ void __launch_bounds__(SCAN_THREADS) scan_kernel() {
    __shared__ int sums[SCAN_THREADS];
    const int t     = threadIdx.x;
    const int start = t * SCAN_CHUNK;
    const int end   = min(start + SCAN_CHUNK, N_NODES);

    int s = 0;
    for (int i = start; i < end; i++) s += g_cnt[i];
    sums[t] = s;
    __syncthreads();

    for (int d = 1; d < SCAN_THREADS; d <<= 1) {
        int v = 0;
        if (t >= d) v = sums[t - d];
        __syncthreads();
        if (t >= d) sums[t] += v;
        __syncthreads();
    }

    int run = sums[t] - s;
    for (int i = start; i < end; i++) {
        g_off[i] = run;
        run += g_cnt[i];
    }
}

// ---------------------------------------------------------------------------
// Kernel D: scatter edges into row-sorted order — ATOMIC-FREE (slot
// precomputed in hist). Pure streaming loads + scattered 8B stores.
// ---------------------------------------------------------------------------
__global__ void __launch_bounds__(256) sort_scatter_kernel(const int* __restrict__ erow,
                                                           const int* __restrict__ ecol,
                                                           const float* __restrict__ eval) {
    int i = blockIdx.x * blockDim.x + threadIdx.x;
    if (i >= N_EDGES) return;
    int p = g_off[erow[i]] + g_idx[i];
    g_edgeS[p] = make_uint2((unsigned)ecol[i], __float_as_uint(eval[i]));
}

// ---------------------------------------------------------------------------
// Kernel E: Y = fp16(X @ W^T) via tensor cores (mma.m16n8k16, fp32 accum).
// Block tile 128x128, K-tile 32. 8 warps: 2 (M) x 4 (N); warp tile 64x32.
// (R6 configuration — the proven best GEMM.)
// ---------------------------------------------------------------------------
#define GBM 128
#define GBN 128
#define GBK 32
#define TSTR 40   // smem row stride in halves (80 B: conflict-free for ldmatrix)

__device__ __forceinline__ uint32_t smem_u32(const void* p) {
    return (uint32_t)__cvta_generic_to_shared(p);
}

__global__ void __launch_bounds__(256) gemm_tc_kernel(const float* __restrict__ X,
                                                      const float* __restrict__ W,
                                                      int M) {
    __shared__ __half As[GBM * TSTR];
    __shared__ __half Bs[GBN * TSTR];

    const int tid  = threadIdx.x;
    const int warp = tid >> 5;
    const int lane = tid & 31;
    const int wm   = warp >> 2;
    const int wn   = warp & 3;
    const int bm0  = blockIdx.y * GBM;
    const int bn0  = blockIdx.x * GBN;

    float acc[4][4][4];
#pragma unroll
    for (int mf = 0; mf < 4; mf++)
#pragma unroll
        for (int nf = 0; nf < 4; nf++)
#pragma unroll
            for (int q = 0; q < 4; q++) acc[mf][nf][q] = 0.0f;

    const int lrow = tid >> 3;
    const int lf4  = tid & 7;

    for (int kk = 0; kk < DIM; kk += GBK) {
#pragma unroll
        for (int p = 0; p < 4; p++) {
            int r  = lrow + p * 32;
            int gm = bm0 + r;
            float4 v = make_float4(0.f, 0.f, 0.f, 0.f);
            if (gm < M)
                v = *reinterpret_cast<const float4*>(X + (size_t)gm * DIM + kk + lf4 * 4);
            __half2 h0 = __floats2half2_rn(v.x, v.y);
            __half2 h1 = __floats2half2_rn(v.z, v.w);
            uint2 pk;
            pk.x = *reinterpret_cast<uint32_t*>(&h0);
            pk.y = *reinterpret_cast<uint32_t*>(&h1);
            *reinterpret_cast<uint2*>(&As[r * TSTR + lf4 * 4]) = pk;
        }
#pragma unroll
        for (int p = 0; p < 4; p++) {
            int r = lrow + p * 32;
            float4 v = *reinterpret_cast<const float4*>(W + (size_t)(bn0 + r) * DIM + kk + lf4 * 4);
            __half2 h0 = __floats2half2_rn(v.x, v.y);
            __half2 h1 = __floats2half2_rn(v.z, v.w);
            uint2 pk;
            pk.x = *reinterpret_cast<uint32_t*>(&h0);
            pk.y = *reinterpret_cast<uint32_t*>(&h1);
            *reinterpret_cast<uint2*>(&Bs[r * TSTR + lf4 * 4]) = pk;
        }
        __syncthreads();

#pragma unroll
        for (int ks = 0; ks < 2; ks++) {
            const int k0 = ks * 16;
            uint32_t a[4][4];
            uint32_t bfr[4][2];

#pragma unroll
            for (int mf = 0; mf < 4; mf++) {
                int row = wm * 64 + mf * 16 + (lane & 15);
                int col = k0 + (lane >> 4) * 8;
                uint32_t addr = smem_u32(&As[row * TSTR + col]);
                asm volatile("ldmatrix.sync.aligned.m8n8.x4.shared.b16 {%0,%1,%2,%3}, [%4];"
                             : "=r"(a[mf][0]), "=r"(a[mf][1]), "=r"(a[mf][2]), "=r"(a[mf][3])
                             : "r"(addr));
            }
#pragma unroll
            for (int nf = 0; nf < 4; nf++) {
                int row = wn * 32 + nf * 8 + (lane & 7);
                int col = k0 + ((lane >> 3) & 1) * 8;
                uint32_t addr = smem_u32(&Bs[row * TSTR + col]);
                asm volatile("ldmatrix.sync.aligned.m8n8.x2.shared.b16 {%0,%1}, [%2];"
                             : "=r"(bfr[nf][0]), "=r"(bfr[nf][1])
                             : "r"(addr));
            }
#pragma unroll
            for (int mf = 0; mf < 4; mf++)
#pragma unroll
                for (int nf = 0; nf < 4; nf++) {
                    asm volatile(
                        "mma.sync.aligned.m16n8k16.row.col.f32.f16.f16.f32 "
                        "{%0,%1,%2,%3}, {%4,%5,%6,%7}, {%8,%9}, {%0,%1,%2,%3};"
                        : "+f"(acc[mf][nf][0]), "+f"(acc[mf][nf][1]),
                          "+f"(acc[mf][nf][2]), "+f"(acc[mf][nf][3])
                        : "r"(a[mf][0]), "r"(a[mf][1]), "r"(a[mf][2]), "r"(a[mf][3]),
                          "r"(bfr[nf][0]), "r"(bfr[nf][1]));
                }
        }
        __syncthreads();
    }

    const int tr = lane >> 2;
    const int tc = lane & 3;
#pragma unroll
    for (int mf = 0; mf < 4; mf++)
#pragma unroll
        for (int nf = 0; nf < 4; nf++) {
            int col2 = (bn0 + wn * 32 + nf * 8) / 2 + tc;
            int r0 = bm0 + wm * 64 + mf * 16 + tr;
            if (r0 < M)
                g_Yh[(size_t)r0 * (DIM / 2) + col2] =
                    __floats2half2_rn(acc[mf][nf][0], acc[mf][nf][1]);
            int r1 = r0 + 8;
            if (r1 < M)
                g_Yh[(size_t)r1 * (DIM / 2) + col2] =
                    __floats2half2_rn(acc[mf][nf][2], acc[mf][nf][3]);
        }
}

// ---------------------------------------------------------------------------
// Kernel F: per-node gather-reduce (R6 form — proven local optimum).
// One warp per node; each lane owns 8 floats (= one uint4 of 8 halves).
// ---------------------------------------------------------------------------
__global__ void __launch_bounds__(256) gather_reduce_kernel(const float* __restrict__ b,
                                                            float* __restrict__ out) {
    const int warp = (blockIdx.x * blockDim.x + threadIdx.x) >> 5;
    const int lane = threadIdx.x & 31;
    if (warp >= N_NODES) return;

    const int start = g_off[warp];
    const int deg   = g_cnt[warp];

    float acc[8] = {0.f, 0.f, 0.f, 0.f, 0.f, 0.f, 0.f, 0.f};

    for (int base = 0; base < deg; base += 32) {
        const int rem = deg - base;
        const int lim = rem < 32 ? rem : 32;
        uint2 e = make_uint2(0u, 0u);
        if (lane < lim) e = g_edgeS[start + base + lane];
#pragma unroll 4
        for (int j = 0; j < lim; j++) {
            const int   cc = (int)__shfl_sync(0xffffffffu, e.x, j);
            const float vv = __uint_as_float(__shfl_sync(0xffffffffu, e.y, j));
            const uint4* src = reinterpret_cast<const uint4*>(g_Yh + (size_t)cc * (DIM / 2));
            uint4 p = src[lane];
            const __half2* h = reinterpret_cast<const __half2*>(&p);
#pragma unroll
            for (int q = 0; q < 4; q++) {
                float2 f = __half22float2(h[q]);
                acc[q * 2 + 0] = fmaf(vv, f.x, acc[q * 2 + 0]);
                acc[q * 2 + 1] = fmaf(vv, f.y, acc[q * 2 + 1]);
            }
        }
    }

    const float4* bv = reinterpret_cast<const float4*>(b);
    float4 b0 = bv[lane * 2];
    float4 b1 = bv[lane * 2 + 1];
    float4 o0 = make_float4(acc[0] + b0.x, acc[1] + b0.y, acc[2] + b0.z, acc[3] + b0.w);
    float4 o1 = make_float4(acc[4] + b1.x, acc[5] + b1.y, acc[6] + b1.z, acc[7] + b1.w);

    float4* dst = reinterpret_cast<float4*>(out + (size_t)warp * DIM);
    dst[lane * 2]     = o0;
    dst[lane * 2 + 1] = o1;
}

// ---------------------------------------------------------------------------
// Launch (single stream — proven best). Inputs: X, edge_row, edge_col,
// edge_val, W, b
// ---------------------------------------------------------------------------
extern "C" void kernel_launch(void* const* d_in, const int* in_sizes, int n_in,
                              void* d_out, int out_size) {
    const float* X    = (const float*)d_in[0];
    const int*   erow = (const int*)  d_in[1];
    const int*   ecol = (const int*)  d_in[2];
    const float* eval = (const float*)d_in[3];
    const float* W    = (const float*)d_in[4];
    const float* b    = (const float*)d_in[5];
    float*       out  = (float*)d_out;

    // 1) counting sort of edges by destination row (scatter is atomic-free)
    zero_kernel<<<(N_NODES + 255) / 256, 256>>>();
    hist_kernel<<<(N_EDGES + 255) / 256, 256>>>(erow);
    scan_kernel<<<1, SCAN_THREADS>>>();
    sort_scatter_kernel<<<(N_EDGES + 255) / 256, 256>>>(erow, ecol, eval);

    // 2) Y = fp16(X @ W^T) on tensor cores (128x128 tile)
    {
        dim3 grid(DIM / GBN, (N_NODES + GBM - 1) / GBM);
        gemm_tc_kernel<<<grid, 256>>>(X, W, N_NODES);
    }

    // 3) out[n] = b + sum val * Y[col]   (atomic-free)
    {
        int warps_per_block = 256 / 32;
        int blocks = (N_NODES + warps_per_block - 1) / warps_per_block;
        gather_reduce_kernel<<<blocks, 256>>>(b, out);
    }
}